// round 1
// baseline (speedup 1.0000x reference)
#include <cuda_runtime.h>
#include <math.h>

// Problem max dims (fixed by the dataset)
#define MAXN 50000
#define MAXE 800000
#define MAXL 1600000

// -------- scratch (device globals: allocation-free contract) --------
__device__ float g_px[(size_t)MAXN * 128];
__device__ float g_fused[(size_t)MAXE * 128];
__device__ float g_agg[(size_t)MAXE * 128];
__device__ float g_h[(size_t)MAXE * 128];
__device__ float g_lcnt[MAXE];
__device__ float g_ncnt[MAXN];
__device__ float g_bnsum[128];
__device__ float g_bnsumsq[128];
__device__ float g_scale[128];
__device__ float g_shift[128];

// ====================================================================
// K1: px[M,128] = x[M,K] @ Wp[128,K]^T   (fp32 SIMT, 64x128 tile)
// ====================================================================
__global__ void k_px(const float* __restrict__ A, const float* __restrict__ W,
                     int M, int K) {
    __shared__ float As[32][64];
    __shared__ float Bs[32][128];
    const int tid = threadIdx.x;
    const int tx = tid & 15;      // 16 col-groups of 8
    const int ty = tid >> 4;      // 8 row-groups of 8
    const int row0 = blockIdx.x * 64;

    float acc[8][8];
#pragma unroll
    for (int i = 0; i < 8; i++)
#pragma unroll
        for (int j = 0; j < 8; j++) acc[i][j] = 0.f;

    for (int kb = 0; kb < K; kb += 32) {
        // load A chunk 64x32 (transposed into As[k][m])
#pragma unroll
        for (int i = tid; i < 512; i += 128) {
            int m = i >> 3;
            int kk = (i & 7) * 4;
            int r = row0 + m;
            float4 v = make_float4(0.f, 0.f, 0.f, 0.f);
            if (r < M) v = *(const float4*)&A[(size_t)r * K + kb + kk];
            As[kk + 0][m] = v.x; As[kk + 1][m] = v.y;
            As[kk + 2][m] = v.z; As[kk + 3][m] = v.w;
        }
        // load W chunk 128x32 into Bs[k][c]
#pragma unroll
        for (int i = tid; i < 1024; i += 128) {
            int c = i >> 3;
            int kk = (i & 7) * 4;
            float4 v = *(const float4*)&W[(size_t)c * K + kb + kk];
            Bs[kk + 0][c] = v.x; Bs[kk + 1][c] = v.y;
            Bs[kk + 2][c] = v.z; Bs[kk + 3][c] = v.w;
        }
        __syncthreads();
#pragma unroll 4
        for (int kk = 0; kk < 32; kk++) {
            float4 a0 = *(float4*)&As[kk][ty * 8];
            float4 a1 = *(float4*)&As[kk][ty * 8 + 4];
            float4 b0 = *(float4*)&Bs[kk][tx * 8];
            float4 b1 = *(float4*)&Bs[kk][tx * 8 + 4];
            float a[8] = {a0.x, a0.y, a0.z, a0.w, a1.x, a1.y, a1.z, a1.w};
            float b[8] = {b0.x, b0.y, b0.z, b0.w, b1.x, b1.y, b1.z, b1.w};
#pragma unroll
            for (int i = 0; i < 8; i++)
#pragma unroll
                for (int j = 0; j < 8; j++) acc[i][j] += a[i] * b[j];
        }
        __syncthreads();
    }
#pragma unroll
    for (int i = 0; i < 8; i++) {
        int r = row0 + ty * 8 + i;
        if (r < M) {
            float4 o0 = make_float4(acc[i][0], acc[i][1], acc[i][2], acc[i][3]);
            float4 o1 = make_float4(acc[i][4], acc[i][5], acc[i][6], acc[i][7]);
            *(float4*)&g_px[(size_t)r * 128 + tx * 8] = o0;
            *(float4*)&g_px[(size_t)r * 128 + tx * 8 + 4] = o1;
        }
    }
}

// ====================================================================
// K2: fused = edge_attr + 0.5*(px[src]+px[dst]); warp per edge
// ====================================================================
__global__ void k_fuse(const float* __restrict__ ea, const int* __restrict__ ei,
                       int E) {
    int t = blockIdx.x * blockDim.x + threadIdx.x;
    int e = t >> 5;
    int lane = t & 31;
    if (e >= E) return;
    int s = ei[e];
    int d = ei[E + e];
    int c = lane * 4;
    float4 a = *(const float4*)&ea[(size_t)e * 128 + c];
    float4 ps = *(const float4*)&g_px[(size_t)s * 128 + c];
    float4 pd = *(const float4*)&g_px[(size_t)d * 128 + c];
    float4 o;
    o.x = a.x + 0.5f * (ps.x + pd.x);
    o.y = a.y + 0.5f * (ps.y + pd.y);
    o.z = a.z + 0.5f * (ps.z + pd.z);
    o.w = a.w + 0.5f * (ps.w + pd.w);
    *(float4*)&g_fused[(size_t)e * 128 + c] = o;
}

// counts
__global__ void k_lcnt(const int* __restrict__ lei, int L) {
    int t = blockIdx.x * blockDim.x + threadIdx.x;
    if (t < L) atomicAdd(&g_lcnt[lei[L + t]], 1.f);
}
__global__ void k_ncnt(const int* __restrict__ ei, int E) {
    int t = blockIdx.x * blockDim.x + threadIdx.x;
    if (t < E) atomicAdd(&g_ncnt[ei[E + t]], 1.f);
}

// ====================================================================
// K3: agg[line_dst] += fused[line_src]; warp per line-edge
// ====================================================================
__global__ void k_scatter(const int* __restrict__ lei, int L) {
    int t = blockIdx.x * blockDim.x + threadIdx.x;
    int l = t >> 5;
    int lane = t & 31;
    if (l >= L) return;
    int s = lei[l];
    int d = lei[L + l];
    int c = lane * 4;
    float4 v = *(const float4*)&g_fused[(size_t)s * 128 + c];
    float* p = &g_agg[(size_t)d * 128 + c];
    atomicAdd(p + 0, v.x);
    atomicAdd(p + 1, v.y);
    atomicAdd(p + 2, v.z);
    atomicAdd(p + 3, v.w);
}

// ====================================================================
// K4: h = PReLU((agg/cnt)@W1^T + b1); store h; accumulate BN stats
// ====================================================================
__global__ void k_hgemm(const float* __restrict__ W, const float* __restrict__ bias,
                        const float* __restrict__ prelu_a, int M) {
    __shared__ float As[32][64];
    __shared__ float Bs[32][128];
    __shared__ float invc[64];
    __shared__ float red[8][128];
    const int K = 128;
    const int tid = threadIdx.x;
    const int tx = tid & 15;
    const int ty = tid >> 4;
    const int row0 = blockIdx.x * 64;

    if (tid < 64) {
        int r = row0 + tid;
        invc[tid] = (r < M) ? (1.f / fmaxf(g_lcnt[r], 1.f)) : 0.f;
    }
    __syncthreads();

    float acc[8][8];
#pragma unroll
    for (int i = 0; i < 8; i++)
#pragma unroll
        for (int j = 0; j < 8; j++) acc[i][j] = 0.f;

    for (int kb = 0; kb < K; kb += 32) {
#pragma unroll
        for (int i = tid; i < 512; i += 128) {
            int m = i >> 3;
            int kk = (i & 7) * 4;
            int r = row0 + m;
            float4 v = make_float4(0.f, 0.f, 0.f, 0.f);
            if (r < M) v = *(const float4*)&g_agg[(size_t)r * K + kb + kk];
            float ic = invc[m];
            As[kk + 0][m] = v.x * ic; As[kk + 1][m] = v.y * ic;
            As[kk + 2][m] = v.z * ic; As[kk + 3][m] = v.w * ic;
        }
#pragma unroll
        for (int i = tid; i < 1024; i += 128) {
            int c = i >> 3;
            int kk = (i & 7) * 4;
            float4 v = *(const float4*)&W[(size_t)c * K + kb + kk];
            Bs[kk + 0][c] = v.x; Bs[kk + 1][c] = v.y;
            Bs[kk + 2][c] = v.z; Bs[kk + 3][c] = v.w;
        }
        __syncthreads();
#pragma unroll 4
        for (int kk = 0; kk < 32; kk++) {
            float4 a0 = *(float4*)&As[kk][ty * 8];
            float4 a1 = *(float4*)&As[kk][ty * 8 + 4];
            float4 b0 = *(float4*)&Bs[kk][tx * 8];
            float4 b1 = *(float4*)&Bs[kk][tx * 8 + 4];
            float a[8] = {a0.x, a0.y, a0.z, a0.w, a1.x, a1.y, a1.z, a1.w};
            float b[8] = {b0.x, b0.y, b0.z, b0.w, b1.x, b1.y, b1.z, b1.w};
#pragma unroll
            for (int i = 0; i < 8; i++)
#pragma unroll
                for (int j = 0; j < 8; j++) acc[i][j] += a[i] * b[j];
        }
        __syncthreads();
    }

    const float alpha = prelu_a[0];
    float bj[8];
#pragma unroll
    for (int j = 0; j < 8; j++) bj[j] = bias[tx * 8 + j];

    float colsum[8], colsq[8];
#pragma unroll
    for (int j = 0; j < 8; j++) { colsum[j] = 0.f; colsq[j] = 0.f; }

#pragma unroll
    for (int i = 0; i < 8; i++) {
        int r = row0 + ty * 8 + i;
        if (r < M) {
            float hv[8];
#pragma unroll
            for (int j = 0; j < 8; j++) {
                float v = acc[i][j] + bj[j];
                v = (v >= 0.f) ? v : alpha * v;
                hv[j] = v;
                colsum[j] += v;
                colsq[j] += v * v;
            }
            *(float4*)&g_h[(size_t)r * 128 + tx * 8] =
                make_float4(hv[0], hv[1], hv[2], hv[3]);
            *(float4*)&g_h[(size_t)r * 128 + tx * 8 + 4] =
                make_float4(hv[4], hv[5], hv[6], hv[7]);
        }
    }

    // block-level channel reduction, then one atomic per channel per block
#pragma unroll
    for (int j = 0; j < 8; j++) red[ty][tx * 8 + j] = colsum[j];
    __syncthreads();
    if (tid < 128) {
        float s = 0.f;
#pragma unroll
        for (int t = 0; t < 8; t++) s += red[t][tid];
        atomicAdd(&g_bnsum[tid], s);
    }
    __syncthreads();
#pragma unroll
    for (int j = 0; j < 8; j++) red[ty][tx * 8 + j] = colsq[j];
    __syncthreads();
    if (tid < 128) {
        float s = 0.f;
#pragma unroll
        for (int t = 0; t < 8; t++) s += red[t][tid];
        atomicAdd(&g_bnsumsq[tid], s);
    }
}

// K5: fold BN into per-channel scale/shift
__global__ void k_bnfin(const float* __restrict__ gamma,
                        const float* __restrict__ beta, float invE) {
    int c = threadIdx.x;
    float mean = g_bnsum[c] * invE;
    float var = g_bnsumsq[c] * invE - mean * mean;
    float sc = rsqrtf(var + 1e-5f) * gamma[c];
    g_scale[c] = sc;
    g_shift[c] = beta[c] - mean * sc;
}

// ====================================================================
// K6: out[dst] += fused + h*scale + shift; warp per edge
// ====================================================================
__global__ void k_final(const int* __restrict__ ei, float* __restrict__ out,
                        int E) {
    int t = blockIdx.x * blockDim.x + threadIdx.x;
    int e = t >> 5;
    int lane = t & 31;
    if (e >= E) return;
    int d = ei[E + e];
    int c = lane * 4;
    float4 f = *(const float4*)&g_fused[(size_t)e * 128 + c];
    float4 h = *(const float4*)&g_h[(size_t)e * 128 + c];
    float4 sc = *(const float4*)&g_scale[c];
    float4 sh = *(const float4*)&g_shift[c];
    float* p = &out[(size_t)d * 128 + c];
    atomicAdd(p + 0, f.x + h.x * sc.x + sh.x);
    atomicAdd(p + 1, f.y + h.y * sc.y + sh.y);
    atomicAdd(p + 2, f.z + h.z * sc.z + sh.z);
    atomicAdd(p + 3, f.w + h.w * sc.w + sh.w);
}

// K7: divide node rows by degree
__global__ void k_div(float* __restrict__ out, int N) {
    int t = blockIdx.x * blockDim.x + threadIdx.x;
    int n = t >> 5;
    int lane = t & 31;
    if (n >= N) return;
    float inv = 1.f / fmaxf(g_ncnt[n], 1.f);
    float4* p = (float4*)&out[(size_t)n * 128 + lane * 4];
    float4 v = *p;
    v.x *= inv; v.y *= inv; v.z *= inv; v.w *= inv;
    *p = v;
}

// ====================================================================
extern "C" void kernel_launch(void* const* d_in, const int* in_sizes, int n_in,
                              void* d_out, int out_size) {
    const float* x     = (const float*)d_in[0];
    const float* ea    = (const float*)d_in[1];
    const float* Wp    = (const float*)d_in[2];
    const float* W1    = (const float*)d_in[3];
    const float* b1    = (const float*)d_in[4];
    const float* pa    = (const float*)d_in[5];
    const float* gamma = (const float*)d_in[6];
    const float* beta  = (const float*)d_in[7];
    const int*   ei    = (const int*)d_in[8];
    const int*   lei   = (const int*)d_in[9];

    const int N = in_sizes[0] / 256;
    const int E = in_sizes[1] / 128;
    const int L = in_sizes[9] / 2;
    float* out = (float*)d_out;

    void *p_agg, *p_lcnt, *p_ncnt, *p_bns, *p_bnss;
    cudaGetSymbolAddress(&p_agg, g_agg);
    cudaGetSymbolAddress(&p_lcnt, g_lcnt);
    cudaGetSymbolAddress(&p_ncnt, g_ncnt);
    cudaGetSymbolAddress(&p_bns, g_bnsum);
    cudaGetSymbolAddress(&p_bnss, g_bnsumsq);

    cudaMemsetAsync(p_agg, 0, (size_t)E * 128 * sizeof(float));
    cudaMemsetAsync(p_lcnt, 0, (size_t)E * sizeof(float));
    cudaMemsetAsync(p_ncnt, 0, (size_t)N * sizeof(float));
    cudaMemsetAsync(p_bns, 0, 128 * sizeof(float));
    cudaMemsetAsync(p_bnss, 0, 128 * sizeof(float));
    cudaMemsetAsync(d_out, 0, (size_t)N * 128 * sizeof(float));

    k_px<<<(N + 63) / 64, 128>>>(x, Wp, N, 256);
    k_fuse<<<(E * 32 + 255) / 256, 256>>>(ea, ei, E);
    k_lcnt<<<(L + 255) / 256, 256>>>(lei, L);
    k_ncnt<<<(E + 255) / 256, 256>>>(ei, E);
    k_scatter<<<((long long)L * 32 + 255) / 256, 256>>>(lei, L);
    k_hgemm<<<(E + 63) / 64, 128>>>(W1, b1, pa, E);
    k_bnfin<<<1, 128>>>(gamma, beta, 1.f / (float)E);
    k_final<<<(E * 32 + 255) / 256, 256>>>(ei, out, E);
    k_div<<<(N * 32 + 255) / 256, 256>>>(out, N);
}

// round 2
// speedup vs baseline: 2.0023x; 2.0023x over previous
#include <cuda_runtime.h>
#include <cuda_bf16.h>
#include <math.h>

#define MAXN 50000
#define MAXE 800000
#define MAXL 1600000

// -------- scratch (device globals: allocation-free contract) --------
__device__ float g_px[(size_t)MAXN * 128];
__device__ float g_fused[(size_t)MAXE * 128];
__device__ float g_aggm[(size_t)MAXE * 128];   // pre-divided segment mean
__device__ float g_h[(size_t)MAXE * 128];
__device__ float g_ncnt[MAXN];
__device__ int   g_lcnt[MAXE];
__device__ int   g_cur[MAXE];
__device__ int   g_off[MAXE + 1];
__device__ int   g_csr[MAXL];
__device__ int   g_bsum[1024];
__device__ float g_bnsum[128];
__device__ float g_bnsumsq[128];
__device__ float g_scale[128];
__device__ float g_shift[128];

// ====================================================================
// Split-bf16 tensor-core GEMM:  C[M,128] = A[M,K] @ W[128,K]^T
// a = a_hi + a_lo (bf16 each); C ~= Ahi*Bhi + Ahi*Blo + Alo*Bhi
// EPI=0: plain store. EPI=1: + bias, PReLU, store.
// ====================================================================
__device__ __forceinline__ void mma_bf16(float* c, const unsigned* a,
                                         unsigned b0, unsigned b1) {
    asm volatile(
        "mma.sync.aligned.m16n8k16.row.col.f32.bf16.bf16.f32 "
        "{%0,%1,%2,%3}, {%4,%5,%6,%7}, {%8,%9}, {%0,%1,%2,%3};"
        : "+f"(c[0]), "+f"(c[1]), "+f"(c[2]), "+f"(c[3])
        : "r"(a[0]), "r"(a[1]), "r"(a[2]), "r"(a[3]), "r"(b0), "r"(b1));
}

#define SMS 40  // smem row stride in bf16 elements (80B = 20 banks, conflict-free)

template <int EPI>
__global__ __launch_bounds__(256) void k_gemm(
    const float* __restrict__ A, const float* __restrict__ W,
    const float* __restrict__ bias, const float* __restrict__ prelu_a,
    float* __restrict__ C, int M, int K) {
    __shared__ __nv_bfloat16 Ah[128][SMS];
    __shared__ __nv_bfloat16 Al[128][SMS];
    __shared__ __nv_bfloat16 Bh[128][SMS];
    __shared__ __nv_bfloat16 Bl[128][SMS];

    const int tid = threadIdx.x;
    const int lane = tid & 31;
    const int wid = tid >> 5;
    const int g = lane >> 2;     // fragment row/col group
    const int t = lane & 3;      // fragment pair index
    const int warp_m = wid & 3;  // 4 warps over 128 rows (32 each)
    const int warp_n = wid >> 2; // 2 warps over 128 cols (64 each)
    const int row0 = blockIdx.x * 128;

    // staging role: each thread loads one row-half-chunk (16 k) per stage
    const int ld_row = tid >> 1;
    const int ld_k = (tid & 1) * 16;

    float acc[2][8][4];
#pragma unroll
    for (int mt = 0; mt < 2; mt++)
#pragma unroll
        for (int nt = 0; nt < 8; nt++)
#pragma unroll
            for (int r = 0; r < 4; r++) acc[mt][nt][r] = 0.f;

    for (int kb = 0; kb < K; kb += 32) {
        // stage A (rows may exceed M -> zeros)
        {
            int r = row0 + ld_row;
            const float* src = &A[(size_t)r * K + kb + ld_k];
#pragma unroll
            for (int j = 0; j < 4; j++) {
                float4 v = make_float4(0.f, 0.f, 0.f, 0.f);
                if (r < M) v = *(const float4*)(src + j * 4);
                float vv[4] = {v.x, v.y, v.z, v.w};
                __nv_bfloat162 hi2, lo2;
#pragma unroll
                for (int p = 0; p < 2; p++) {
                    __nv_bfloat16 h0 = __float2bfloat16_rn(vv[2 * p]);
                    __nv_bfloat16 h1 = __float2bfloat16_rn(vv[2 * p + 1]);
                    __nv_bfloat16 l0 = __float2bfloat16_rn(vv[2 * p] - __bfloat162float(h0));
                    __nv_bfloat16 l1 = __float2bfloat16_rn(vv[2 * p + 1] - __bfloat162float(h1));
                    hi2.x = h0; hi2.y = h1; lo2.x = l0; lo2.y = l1;
                    *(__nv_bfloat162*)&Ah[ld_row][ld_k + j * 4 + 2 * p] = hi2;
                    *(__nv_bfloat162*)&Al[ld_row][ld_k + j * 4 + 2 * p] = lo2;
                }
            }
        }
        // stage W (always 128 full rows)
        {
            const float* src = &W[(size_t)ld_row * K + kb + ld_k];
#pragma unroll
            for (int j = 0; j < 4; j++) {
                float4 v = *(const float4*)(src + j * 4);
                float vv[4] = {v.x, v.y, v.z, v.w};
                __nv_bfloat162 hi2, lo2;
#pragma unroll
                for (int p = 0; p < 2; p++) {
                    __nv_bfloat16 h0 = __float2bfloat16_rn(vv[2 * p]);
                    __nv_bfloat16 h1 = __float2bfloat16_rn(vv[2 * p + 1]);
                    __nv_bfloat16 l0 = __float2bfloat16_rn(vv[2 * p] - __bfloat162float(h0));
                    __nv_bfloat16 l1 = __float2bfloat16_rn(vv[2 * p + 1] - __bfloat162float(h1));
                    hi2.x = h0; hi2.y = h1; lo2.x = l0; lo2.y = l1;
                    *(__nv_bfloat162*)&Bh[ld_row][ld_k + j * 4 + 2 * p] = hi2;
                    *(__nv_bfloat162*)&Bl[ld_row][ld_k + j * 4 + 2 * p] = lo2;
                }
            }
        }
        __syncthreads();

#pragma unroll
        for (int kk = 0; kk < 32; kk += 16) {
            unsigned a_hi[2][4], a_lo[2][4];
#pragma unroll
            for (int mt = 0; mt < 2; mt++) {
                int m0 = warp_m * 32 + mt * 16 + g;
                a_hi[mt][0] = *(const unsigned*)&Ah[m0][kk + 2 * t];
                a_hi[mt][1] = *(const unsigned*)&Ah[m0 + 8][kk + 2 * t];
                a_hi[mt][2] = *(const unsigned*)&Ah[m0][kk + 2 * t + 8];
                a_hi[mt][3] = *(const unsigned*)&Ah[m0 + 8][kk + 2 * t + 8];
                a_lo[mt][0] = *(const unsigned*)&Al[m0][kk + 2 * t];
                a_lo[mt][1] = *(const unsigned*)&Al[m0 + 8][kk + 2 * t];
                a_lo[mt][2] = *(const unsigned*)&Al[m0][kk + 2 * t + 8];
                a_lo[mt][3] = *(const unsigned*)&Al[m0 + 8][kk + 2 * t + 8];
            }
#pragma unroll
            for (int nt = 0; nt < 8; nt++) {
                int n = warp_n * 64 + nt * 8 + g;
                unsigned bh0 = *(const unsigned*)&Bh[n][kk + 2 * t];
                unsigned bh1 = *(const unsigned*)&Bh[n][kk + 2 * t + 8];
                unsigned bl0 = *(const unsigned*)&Bl[n][kk + 2 * t];
                unsigned bl1 = *(const unsigned*)&Bl[n][kk + 2 * t + 8];
#pragma unroll
                for (int mt = 0; mt < 2; mt++) {
                    mma_bf16(acc[mt][nt], a_hi[mt], bh0, bh1);
                    mma_bf16(acc[mt][nt], a_hi[mt], bl0, bl1);
                    mma_bf16(acc[mt][nt], a_lo[mt], bh0, bh1);
                }
            }
        }
        __syncthreads();
    }

    // epilogue
    float alpha = 0.f;
    if (EPI == 1) alpha = prelu_a[0];
#pragma unroll
    for (int nt = 0; nt < 8; nt++) {
        int col = warp_n * 64 + nt * 8 + 2 * t;
        float b0 = 0.f, b1 = 0.f;
        if (EPI == 1) { b0 = bias[col]; b1 = bias[col + 1]; }
#pragma unroll
        for (int mt = 0; mt < 2; mt++) {
            int r0 = row0 + warp_m * 32 + mt * 16 + g;
            int r1 = r0 + 8;
            float v0 = acc[mt][nt][0], v1 = acc[mt][nt][1];
            float v2 = acc[mt][nt][2], v3 = acc[mt][nt][3];
            if (EPI == 1) {
                v0 += b0; v1 += b1; v2 += b0; v3 += b1;
                v0 = (v0 >= 0.f) ? v0 : alpha * v0;
                v1 = (v1 >= 0.f) ? v1 : alpha * v1;
                v2 = (v2 >= 0.f) ? v2 : alpha * v2;
                v3 = (v3 >= 0.f) ? v3 : alpha * v3;
            }
            if (r0 < M) *(float2*)&C[(size_t)r0 * 128 + col] = make_float2(v0, v1);
            if (r1 < M) *(float2*)&C[(size_t)r1 * 128 + col] = make_float2(v2, v3);
        }
    }
}

// ====================================================================
// K2: fused = edge_attr + 0.5*(px[src]+px[dst]); also node degree count
// ====================================================================
__global__ void k_fuse(const float* __restrict__ ea, const int* __restrict__ ei,
                       int E) {
    int tt = blockIdx.x * blockDim.x + threadIdx.x;
    int e = tt >> 5;
    int lane = tt & 31;
    if (e >= E) return;
    int s = ei[e];
    int d = ei[E + e];
    if (lane == 0) atomicAdd(&g_ncnt[d], 1.f);
    int c = lane * 4;
    float4 a = *(const float4*)&ea[(size_t)e * 128 + c];
    float4 ps = *(const float4*)&g_px[(size_t)s * 128 + c];
    float4 pd = *(const float4*)&g_px[(size_t)d * 128 + c];
    float4 o;
    o.x = a.x + 0.5f * (ps.x + pd.x);
    o.y = a.y + 0.5f * (ps.y + pd.y);
    o.z = a.z + 0.5f * (ps.z + pd.z);
    o.w = a.w + 0.5f * (ps.w + pd.w);
    *(float4*)&g_fused[(size_t)e * 128 + c] = o;
}

// ---------------- CSR build: count -> scan -> fill ----------------
__global__ void k_lcnt(const int* __restrict__ lei, int L) {
    int tt = blockIdx.x * blockDim.x + threadIdx.x;
    if (tt < L) atomicAdd(&g_lcnt[lei[L + tt]], 1);
}

__global__ void k_scan1(int E) {
    __shared__ int s[256];
    int tid = threadIdx.x;
    int base = blockIdx.x * 1024 + tid * 4;
    int v[4], p[4];
    int tot = 0;
#pragma unroll
    for (int j = 0; j < 4; j++) {
        v[j] = (base + j < E) ? g_lcnt[base + j] : 0;
        p[j] = tot;
        tot += v[j];
    }
    s[tid] = tot;
    __syncthreads();
    for (int d = 1; d < 256; d <<= 1) {
        int tmp = (tid >= d) ? s[tid - d] : 0;
        __syncthreads();
        s[tid] += tmp;
        __syncthreads();
    }
    int excl = s[tid] - tot;
#pragma unroll
    for (int j = 0; j < 4; j++)
        if (base + j < E) g_off[base + j] = excl + p[j];
    if (tid == 255) g_bsum[blockIdx.x] = s[255];
}

__global__ void k_scan2(int nb, int E, int L) {
    __shared__ int s[1024];
    int tid = threadIdx.x;
    int v = (tid < nb) ? g_bsum[tid] : 0;
    s[tid] = v;
    __syncthreads();
    for (int d = 1; d < 1024; d <<= 1) {
        int tmp = (tid >= d) ? s[tid - d] : 0;
        __syncthreads();
        s[tid] += tmp;
        __syncthreads();
    }
    if (tid < nb) g_bsum[tid] = s[tid] - v;  // exclusive
    if (tid == 0) g_off[E] = L;
}

__global__ void k_scan3(int E) {
    int i = blockIdx.x * blockDim.x + threadIdx.x;
    if (i < E) g_off[i] += g_bsum[i >> 10];
}

__global__ void k_fill(const int* __restrict__ lei, int L) {
    int l = blockIdx.x * blockDim.x + threadIdx.x;
    if (l >= L) return;
    int d = lei[L + l];
    int pos = g_off[d] + atomicAdd(&g_cur[d], 1);
    g_csr[pos] = lei[l];
}

// ---------------- gather-based segment mean ----------------
__global__ void k_agg(int E) {
    int tt = blockIdx.x * blockDim.x + threadIdx.x;
    int e = tt >> 5;
    int lane = tt & 31;
    if (e >= E) return;
    int st = g_off[e];
    int cnt = g_off[e + 1] - st;
    int c = lane * 4;
    float4 s = make_float4(0.f, 0.f, 0.f, 0.f);
    for (int i = 0; i < cnt; i++) {
        int se = g_csr[st + i];
        float4 v = *(const float4*)&g_fused[(size_t)se * 128 + c];
        s.x += v.x; s.y += v.y; s.z += v.z; s.w += v.w;
    }
    float inv = 1.f / (float)max(cnt, 1);
    s.x *= inv; s.y *= inv; s.z *= inv; s.w *= inv;
    *(float4*)&g_aggm[(size_t)e * 128 + c] = s;
}

// ---------------- BN stats over g_h ----------------
__global__ void k_bnstat(int E) {
    __shared__ float ss[128], sq[128];
    int tid = threadIdx.x;
    if (tid < 128) { ss[tid] = 0.f; sq[tid] = 0.f; }
    __syncthreads();
    int col = (tid & 31) * 4;
    int rbase = blockIdx.x * 1024 + (tid >> 5);
    float4 s = make_float4(0.f, 0.f, 0.f, 0.f);
    float4 q = make_float4(0.f, 0.f, 0.f, 0.f);
    for (int i = 0; i < 128; i++) {
        int r = rbase + i * 8;
        if (r < E) {
            float4 v = *(const float4*)&g_h[(size_t)r * 128 + col];
            s.x += v.x; s.y += v.y; s.z += v.z; s.w += v.w;
            q.x += v.x * v.x; q.y += v.y * v.y;
            q.z += v.z * v.z; q.w += v.w * v.w;
        }
    }
    atomicAdd(&ss[col + 0], s.x); atomicAdd(&ss[col + 1], s.y);
    atomicAdd(&ss[col + 2], s.z); atomicAdd(&ss[col + 3], s.w);
    atomicAdd(&sq[col + 0], q.x); atomicAdd(&sq[col + 1], q.y);
    atomicAdd(&sq[col + 2], q.z); atomicAdd(&sq[col + 3], q.w);
    __syncthreads();
    if (tid < 128) {
        atomicAdd(&g_bnsum[tid], ss[tid]);
        atomicAdd(&g_bnsumsq[tid], sq[tid]);
    }
}

__global__ void k_bnfin(const float* __restrict__ gamma,
                        const float* __restrict__ beta, float invE) {
    int c = threadIdx.x;
    float mean = g_bnsum[c] * invE;
    float var = g_bnsumsq[c] * invE - mean * mean;
    float sc = rsqrtf(var + 1e-5f) * gamma[c];
    g_scale[c] = sc;
    g_shift[c] = beta[c] - mean * sc;
}

// ---------------- final scatter to nodes (vector red) ----------------
__global__ void k_final(const int* __restrict__ ei, float* __restrict__ out,
                        int E) {
    int tt = blockIdx.x * blockDim.x + threadIdx.x;
    int e = tt >> 5;
    int lane = tt & 31;
    if (e >= E) return;
    int d = ei[E + e];
    int c = lane * 4;
    float4 f = *(const float4*)&g_fused[(size_t)e * 128 + c];
    float4 h = *(const float4*)&g_h[(size_t)e * 128 + c];
    float4 sc = *(const float4*)&g_scale[c];
    float4 sh = *(const float4*)&g_shift[c];
    float4 r;
    r.x = f.x + h.x * sc.x + sh.x;
    r.y = f.y + h.y * sc.y + sh.y;
    r.z = f.z + h.z * sc.z + sh.z;
    r.w = f.w + h.w * sc.w + sh.w;
    float* p = &out[(size_t)d * 128 + c];
    asm volatile("red.global.add.v4.f32 [%0], {%1,%2,%3,%4};"
                 :: "l"(p), "f"(r.x), "f"(r.y), "f"(r.z), "f"(r.w)
                 : "memory");
}

__global__ void k_div(float* __restrict__ out, int N) {
    int tt = blockIdx.x * blockDim.x + threadIdx.x;
    int n = tt >> 5;
    int lane = tt & 31;
    if (n >= N) return;
    float inv = 1.f / fmaxf(g_ncnt[n], 1.f);
    float4* p = (float4*)&out[(size_t)n * 128 + lane * 4];
    float4 v = *p;
    v.x *= inv; v.y *= inv; v.z *= inv; v.w *= inv;
    *p = v;
}

// ====================================================================
extern "C" void kernel_launch(void* const* d_in, const int* in_sizes, int n_in,
                              void* d_out, int out_size) {
    const float* x     = (const float*)d_in[0];
    const float* ea    = (const float*)d_in[1];
    const float* Wp    = (const float*)d_in[2];
    const float* W1    = (const float*)d_in[3];
    const float* b1    = (const float*)d_in[4];
    const float* pa    = (const float*)d_in[5];
    const float* gamma = (const float*)d_in[6];
    const float* beta  = (const float*)d_in[7];
    const int*   ei    = (const int*)d_in[8];
    const int*   lei   = (const int*)d_in[9];

    const int N = in_sizes[0] / 256;
    const int E = in_sizes[1] / 128;
    const int L = in_sizes[9] / 2;
    float* out = (float*)d_out;

    void *p_lcnt, *p_cur, *p_ncnt, *p_bns, *p_bnss, *p_px, *p_aggm, *p_h;
    cudaGetSymbolAddress(&p_lcnt, g_lcnt);
    cudaGetSymbolAddress(&p_cur, g_cur);
    cudaGetSymbolAddress(&p_ncnt, g_ncnt);
    cudaGetSymbolAddress(&p_bns, g_bnsum);
    cudaGetSymbolAddress(&p_bnss, g_bnsumsq);
    cudaGetSymbolAddress(&p_px, g_px);
    cudaGetSymbolAddress(&p_aggm, g_aggm);
    cudaGetSymbolAddress(&p_h, g_h);

    cudaMemsetAsync(p_lcnt, 0, (size_t)E * sizeof(int));
    cudaMemsetAsync(p_cur, 0, (size_t)E * sizeof(int));
    cudaMemsetAsync(p_ncnt, 0, (size_t)N * sizeof(float));
    cudaMemsetAsync(p_bns, 0, 128 * sizeof(float));
    cudaMemsetAsync(p_bnss, 0, 128 * sizeof(float));
    cudaMemsetAsync(d_out, 0, (size_t)N * 128 * sizeof(float));

    const int nb = (E + 1023) / 1024;

    k_gemm<0><<<(N + 127) / 128, 256>>>(x, Wp, nullptr, nullptr, (float*)p_px, N, 256);
    k_fuse<<<(E * 32 + 255) / 256, 256>>>(ea, ei, E);
    k_lcnt<<<(L + 255) / 256, 256>>>(lei, L);
    k_scan1<<<nb, 256>>>(E);
    k_scan2<<<1, 1024>>>(nb, E, L);
    k_scan3<<<(E + 255) / 256, 256>>>(E);
    k_fill<<<(L + 255) / 256, 256>>>(lei, L);
    k_agg<<<(E * 32 + 255) / 256, 256>>>(E);
    k_gemm<1><<<(E + 127) / 128, 256>>>((const float*)p_aggm, W1, b1, pa, (float*)p_h, E, 128);
    k_bnstat<<<nb, 256>>>(E);
    k_bnfin<<<1, 128>>>(gamma, beta, 1.f / (float)E);
    k_final<<<(E * 32 + 255) / 256, 256>>>(ei, out, E);
    k_div<<<(N * 32 + 255) / 256, 256>>>(out, N);
}